// round 1
// baseline (speedup 1.0000x reference)
#include <cuda_runtime.h>
#include <cuda_bf16.h>
#include <math.h>

#define NB   4
#define NS   160
#define NSS  (160*160)
#define NVOX (160*160*160)   // 4,096,000 per batch
#define ZCH  40              // chunk along swept axis (4 chunks)

// 1D gaussian taps, sigma=5, radius=4: exp(-i^2/50)
#define G_TAPS {0.72614904f,0.83527021f,0.92311635f,0.98019867f,1.0f,\
                0.98019867f,0.92311635f,0.83527021f,0.72614904f}

// scratch (allocation-free rule: __device__ globals)
__device__ double g_S[NB * 3];          // per batch: sum(p), sum(inp*p), sum(inp)
__device__ double g_acc[4];             // N0, D0, N1, D1
__device__ float4 g_bufA[(size_t)NB * NVOX];
__device__ float4 g_bufB[(size_t)NB * NVOX];

__global__ void k_init() {
    int t = threadIdx.x;
    if (t < NB * 3) g_S[t] = 0.0;
    if (t < 4) g_acc[t] = 0.0;
}

__global__ void k_reduce(const float* __restrict__ lab, const float* __restrict__ inp) {
    int b = blockIdx.y;
    const float* L = lab + (size_t)b * NVOX;
    const float* V = inp + (size_t)b * NVOX;
    double sp = 0.0, sip = 0.0, si = 0.0;
    int stride = blockDim.x * gridDim.x;
    for (int i = blockIdx.x * blockDim.x + threadIdx.x; i < NVOX; i += stride) {
        float p = L[i];
        float v = V[i];
        sp  += (double)p;
        sip += (double)(v * p);
        si  += (double)v;
    }
    #pragma unroll
    for (int o = 16; o > 0; o >>= 1) {
        sp  += __shfl_down_sync(0xffffffffu, sp,  o);
        sip += __shfl_down_sync(0xffffffffu, sip, o);
        si  += __shfl_down_sync(0xffffffffu, si,  o);
    }
    __shared__ double sm[3][8];
    int w = threadIdx.x >> 5, l = threadIdx.x & 31;
    if (l == 0) { sm[0][w] = sp; sm[1][w] = sip; sm[2][w] = si; }
    __syncthreads();
    if (threadIdx.x == 0) {
        double a = 0, c = 0, d = 0;
        int nw = blockDim.x >> 5;
        for (int i = 0; i < nw; i++) { a += sm[0][i]; c += sm[1][i]; d += sm[2][i]; }
        atomicAdd(&g_S[b * 3 + 0], a);
        atomicAdd(&g_S[b * 3 + 1], c);
        atomicAdd(&g_S[b * 3 + 2], d);
    }
}

// Pass 1: compute w0/w1 on the fly, convolve along z (sliding ring), write float4 field.
__global__ void __launch_bounds__(NS) k_genz(const float* __restrict__ lab,
                                             const float* __restrict__ inp) {
    const float G[9] = G_TAPS;
    int x  = threadIdx.x;
    int y  = blockIdx.x;
    int zc = blockIdx.y;
    int b  = blockIdx.z;

    const double Nv = (double)NVOX;
    double sp  = g_S[b * 3 + 0];
    double sip = g_S[b * 3 + 1];
    double si  = g_S[b * 3 + 2];
    float m0 = (float)((sip / Nv) / (sp / Nv + 1e-5));
    float m1 = (float)(((si - sip) / Nv) / ((Nv - sp) / Nv + 1e-5));

    int z0 = zc * ZCH;
    float4 ring[9];
    #pragma unroll
    for (int i = 0; i < 9; i++) ring[i] = make_float4(0.f, 0.f, 0.f, 0.f);

    size_t bbase  = (size_t)b * NVOX;
    int    rowoff = y * NS + x;

    for (int z = z0 - 4; z < z0 + ZCH + 4; ++z) {
        float4 wv = make_float4(0.f, 0.f, 0.f, 0.f);
        if (z >= 0 && z < NS) {
            size_t idx = bbase + (size_t)z * NSS + rowoff;
            float p = lab[idx];
            float v = inp[idx];
            float d0 = v - m0; float t0 = d0 * d0; float w0 = __expf(-t0 * t0);
            float d1 = v - m1; float t1 = d1 * d1; float w1 = __expf(-t1 * t1);
            wv = make_float4(w0, p * w0, w1, (1.f - p) * w1);
        }
        #pragma unroll
        for (int i = 0; i < 8; i++) ring[i] = ring[i + 1];
        ring[8] = wv;
        int zo = z - 4;
        if (zo >= z0) {
            float4 o = make_float4(0.f, 0.f, 0.f, 0.f);
            #pragma unroll
            for (int i = 0; i < 9; i++) {
                o.x += G[i] * ring[i].x;
                o.y += G[i] * ring[i].y;
                o.z += G[i] * ring[i].z;
                o.w += G[i] * ring[i].w;
            }
            g_bufA[bbase + (size_t)zo * NSS + rowoff] = o;
        }
    }
}

// Pass 2: convolve along y (sliding ring), bufA -> bufB.
__global__ void __launch_bounds__(NS) k_convy() {
    const float G[9] = G_TAPS;
    int x  = threadIdx.x;
    int z  = blockIdx.x;
    int yc = blockIdx.y;
    int b  = blockIdx.z;

    int y0 = yc * ZCH;
    float4 ring[9];
    #pragma unroll
    for (int i = 0; i < 9; i++) ring[i] = make_float4(0.f, 0.f, 0.f, 0.f);

    size_t sbase = (size_t)b * NVOX + (size_t)z * NSS + x;

    for (int y = y0 - 4; y < y0 + ZCH + 4; ++y) {
        float4 wv = make_float4(0.f, 0.f, 0.f, 0.f);
        if (y >= 0 && y < NS) wv = g_bufA[sbase + (size_t)y * NS];
        #pragma unroll
        for (int i = 0; i < 8; i++) ring[i] = ring[i + 1];
        ring[8] = wv;
        int yo = y - 4;
        if (yo >= y0) {
            float4 o = make_float4(0.f, 0.f, 0.f, 0.f);
            #pragma unroll
            for (int i = 0; i < 9; i++) {
                o.x += G[i] * ring[i].x;
                o.y += G[i] * ring[i].y;
                o.z += G[i] * ring[i].z;
                o.w += G[i] * ring[i].w;
            }
            g_bufB[sbase + (size_t)yo * NS] = o;
        }
    }
}

// Pass 3: convolve along x in smem row, dot with class probs, global reduce.
__global__ void __launch_bounds__(NS) k_convx_dot(const float* __restrict__ lab) {
    const float G[9] = G_TAPS;
    int x  = threadIdx.x;
    int z  = blockIdx.x;
    int yc = blockIdx.y;
    int b  = blockIdx.z;

    __shared__ float4 row[NS];
    float n0 = 0.f, d0 = 0.f, n1 = 0.f, d1 = 0.f;
    size_t sbase = (size_t)b * NVOX + (size_t)z * NSS;

    for (int y = yc * ZCH; y < yc * ZCH + ZCH; ++y) {
        size_t ridx = sbase + (size_t)y * NS;
        row[x] = g_bufB[ridx + x];
        __syncthreads();
        float4 c = make_float4(0.f, 0.f, 0.f, 0.f);
        #pragma unroll
        for (int i = 0; i < 9; i++) {
            int xx = x + i - 4;
            if (xx >= 0 && xx < NS) {
                float4 r = row[xx];
                c.x += G[i] * r.x;
                c.y += G[i] * r.y;
                c.z += G[i] * r.z;
                c.w += G[i] * r.w;
            }
        }
        float p = lab[ridx + x];
        d0 += p * c.x;
        n0 += p * c.y;
        d1 += (1.f - p) * c.z;
        n1 += (1.f - p) * c.w;
        __syncthreads();
    }

    double vn0 = n0, vd0 = d0, vn1 = n1, vd1 = d1;
    #pragma unroll
    for (int o = 16; o > 0; o >>= 1) {
        vn0 += __shfl_down_sync(0xffffffffu, vn0, o);
        vd0 += __shfl_down_sync(0xffffffffu, vd0, o);
        vn1 += __shfl_down_sync(0xffffffffu, vn1, o);
        vd1 += __shfl_down_sync(0xffffffffu, vd1, o);
    }
    __shared__ double sm[4][5];
    int w = threadIdx.x >> 5, l = threadIdx.x & 31;
    if (l == 0) { sm[0][w] = vn0; sm[1][w] = vd0; sm[2][w] = vn1; sm[3][w] = vd1; }
    __syncthreads();
    if (threadIdx.x == 0) {
        double a = 0, bq = 0, c = 0, dq = 0;
        for (int i = 0; i < 5; i++) { a += sm[0][i]; bq += sm[1][i]; c += sm[2][i]; dq += sm[3][i]; }
        atomicAdd(&g_acc[0], a);   // N0
        atomicAdd(&g_acc[1], bq);  // D0
        atomicAdd(&g_acc[2], c);   // N1
        atomicAdd(&g_acc[3], dq);  // D1
    }
}

__global__ void k_final(float* out) {
    double loss = fabs(g_acc[0] / (g_acc[1] + 1e-6)) + fabs(g_acc[2] / (g_acc[3] + 1e-6));
    out[0] = (float)(2.0 - loss);
}

extern "C" void kernel_launch(void* const* d_in, const int* in_sizes, int n_in,
                              void* d_out, int out_size) {
    const float* lab = (const float*)d_in[0];   // labels
    const float* inp = (const float*)d_in[1];   // inputs
    float* out = (float*)d_out;

    k_init<<<1, 32>>>();
    k_reduce<<<dim3(256, NB), 256>>>(lab, inp);
    k_genz<<<dim3(NS, NS / ZCH, NB), NS>>>(lab, inp);
    k_convy<<<dim3(NS, NS / ZCH, NB), NS>>>();
    k_convx_dot<<<dim3(NS, NS / ZCH, NB), NS>>>(lab);
    k_final<<<1, 1>>>(out);
}

// round 2
// speedup vs baseline: 1.5662x; 1.5662x over previous
#include <cuda_runtime.h>
#include <cuda_fp16.h>
#include <math.h>

#define NB   4
#define NS   160
#define NSS  (160*160)
#define NVOX (160*160*160)   // 4,096,000 per batch
#define ZCH  40              // chunk along swept axis (4 chunks)

// 1D gaussian taps, sigma=5, radius=4: exp(-i^2/50)
#define G_TAPS {0.72614904f,0.83527021f,0.92311635f,0.98019867f,1.0f,\
                0.98019867f,0.92311635f,0.83527021f,0.72614904f}

struct h4 { __half2 a, b; };   // (w0, p*w0, w1, (1-p)*w1) packed fp16

__device__ double g_S[NB * 3];          // per batch: sum(p), sum(inp*p), sum(inp)
__device__ double g_acc[4];             // N0, D0, N1, D1
__device__ h4 g_bufA[(size_t)NB * NVOX];

__global__ void k_init() {
    int t = threadIdx.x;
    if (t < NB * 3) g_S[t] = 0.0;
    if (t < 4) g_acc[t] = 0.0;
}

__global__ void k_reduce(const float* __restrict__ lab, const float* __restrict__ inp) {
    int b = blockIdx.y;
    const float4* L = (const float4*)(lab + (size_t)b * NVOX);
    const float4* V = (const float4*)(inp + (size_t)b * NVOX);
    double sp = 0.0, sip = 0.0, si = 0.0;
    int n4 = NVOX / 4;
    int stride = blockDim.x * gridDim.x;
    for (int i = blockIdx.x * blockDim.x + threadIdx.x; i < n4; i += stride) {
        float4 p = L[i];
        float4 v = V[i];
        sp  += (double)(p.x + p.y + p.z + p.w);
        sip += (double)(v.x * p.x + v.y * p.y + v.z * p.z + v.w * p.w);
        si  += (double)(v.x + v.y + v.z + v.w);
    }
    #pragma unroll
    for (int o = 16; o > 0; o >>= 1) {
        sp  += __shfl_down_sync(0xffffffffu, sp,  o);
        sip += __shfl_down_sync(0xffffffffu, sip, o);
        si  += __shfl_down_sync(0xffffffffu, si,  o);
    }
    __shared__ double sm[3][8];
    int w = threadIdx.x >> 5, l = threadIdx.x & 31;
    if (l == 0) { sm[0][w] = sp; sm[1][w] = sip; sm[2][w] = si; }
    __syncthreads();
    if (threadIdx.x == 0) {
        double a = 0, c = 0, d = 0;
        int nw = blockDim.x >> 5;
        for (int i = 0; i < nw; i++) { a += sm[0][i]; c += sm[1][i]; d += sm[2][i]; }
        atomicAdd(&g_S[b * 3 + 0], a);
        atomicAdd(&g_S[b * 3 + 1], c);
        atomicAdd(&g_S[b * 3 + 2], d);
    }
}

// Pass 1: compute w0/w1 on the fly, convolve along z (sliding ring), write fp16x4 field.
__global__ void __launch_bounds__(NS) k_genz(const float* __restrict__ lab,
                                             const float* __restrict__ inp) {
    const float G[9] = G_TAPS;
    int x  = threadIdx.x;
    int y  = blockIdx.x;
    int zc = blockIdx.y;
    int b  = blockIdx.z;

    const double Nv = (double)NVOX;
    double sp  = g_S[b * 3 + 0];
    double sip = g_S[b * 3 + 1];
    double si  = g_S[b * 3 + 2];
    float m0 = (float)((sip / Nv) / (sp / Nv + 1e-5));
    float m1 = (float)(((si - sip) / Nv) / ((Nv - sp) / Nv + 1e-5));

    int z0 = zc * ZCH;
    float4 ring[9];
    #pragma unroll
    for (int i = 0; i < 9; i++) ring[i] = make_float4(0.f, 0.f, 0.f, 0.f);

    size_t bbase  = (size_t)b * NVOX;
    int    rowoff = y * NS + x;

    for (int z = z0 - 4; z < z0 + ZCH + 4; ++z) {
        float4 wv = make_float4(0.f, 0.f, 0.f, 0.f);
        if (z >= 0 && z < NS) {
            size_t idx = bbase + (size_t)z * NSS + rowoff;
            float p = lab[idx];
            float v = inp[idx];
            float d0 = v - m0; float t0 = d0 * d0; float w0 = __expf(-t0 * t0);
            float d1 = v - m1; float t1 = d1 * d1; float w1 = __expf(-t1 * t1);
            wv = make_float4(w0, p * w0, w1, (1.f - p) * w1);
        }
        #pragma unroll
        for (int i = 0; i < 8; i++) ring[i] = ring[i + 1];
        ring[8] = wv;
        int zo = z - 4;
        if (zo >= z0) {
            float4 o = make_float4(0.f, 0.f, 0.f, 0.f);
            #pragma unroll
            for (int i = 0; i < 9; i++) {
                o.x += G[i] * ring[i].x;
                o.y += G[i] * ring[i].y;
                o.z += G[i] * ring[i].z;
                o.w += G[i] * ring[i].w;
            }
            h4 h;
            h.a = __floats2half2_rn(o.x, o.y);
            h.b = __floats2half2_rn(o.z, o.w);
            g_bufA[bbase + (size_t)zo * NSS + rowoff] = h;
        }
    }
}

// Pass 2 (fused): y-conv via per-thread ring, x-conv via smem row, dot with class
// probs, global reduce. Eliminates the second scratch buffer entirely.
__global__ void __launch_bounds__(NS) k_convyx_dot(const float* __restrict__ lab) {
    const float G[9] = G_TAPS;
    int x  = threadIdx.x;
    int z  = blockIdx.x;
    int yc = blockIdx.y;
    int b  = blockIdx.z;

    int y0 = yc * ZCH;
    float4 ring[9];
    #pragma unroll
    for (int i = 0; i < 9; i++) ring[i] = make_float4(0.f, 0.f, 0.f, 0.f);

    __shared__ float4 row[NS];
    float n0 = 0.f, d0 = 0.f, n1 = 0.f, d1 = 0.f;

    size_t pbase = (size_t)b * NVOX + (size_t)z * NSS;   // plane base
    size_t sbase = pbase + x;

    for (int y = y0 - 4; y < y0 + ZCH + 4; ++y) {
        float4 wv = make_float4(0.f, 0.f, 0.f, 0.f);
        if (y >= 0 && y < NS) {
            h4 h = g_bufA[sbase + (size_t)y * NS];
            float2 fa = __half22float2(h.a);
            float2 fb = __half22float2(h.b);
            wv = make_float4(fa.x, fa.y, fb.x, fb.y);
        }
        #pragma unroll
        for (int i = 0; i < 8; i++) ring[i] = ring[i + 1];
        ring[8] = wv;
        int yo = y - 4;
        if (yo >= y0) {
            float4 o = make_float4(0.f, 0.f, 0.f, 0.f);
            #pragma unroll
            for (int i = 0; i < 9; i++) {
                o.x += G[i] * ring[i].x;
                o.y += G[i] * ring[i].y;
                o.z += G[i] * ring[i].z;
                o.w += G[i] * ring[i].w;
            }
            row[x] = o;
            __syncthreads();
            float4 c = make_float4(0.f, 0.f, 0.f, 0.f);
            #pragma unroll
            for (int i = 0; i < 9; i++) {
                int xx = x + i - 4;
                if (xx >= 0 && xx < NS) {
                    float4 r = row[xx];
                    c.x += G[i] * r.x;
                    c.y += G[i] * r.y;
                    c.z += G[i] * r.z;
                    c.w += G[i] * r.w;
                }
            }
            float p = lab[pbase + (size_t)yo * NS + x];
            d0 += p * c.x;
            n0 += p * c.y;
            d1 += (1.f - p) * c.z;
            n1 += (1.f - p) * c.w;
            __syncthreads();
        }
    }

    double vn0 = n0, vd0 = d0, vn1 = n1, vd1 = d1;
    #pragma unroll
    for (int o = 16; o > 0; o >>= 1) {
        vn0 += __shfl_down_sync(0xffffffffu, vn0, o);
        vd0 += __shfl_down_sync(0xffffffffu, vd0, o);
        vn1 += __shfl_down_sync(0xffffffffu, vn1, o);
        vd1 += __shfl_down_sync(0xffffffffu, vd1, o);
    }
    __shared__ double sm[4][5];
    int w = threadIdx.x >> 5, l = threadIdx.x & 31;
    if (l == 0) { sm[0][w] = vn0; sm[1][w] = vd0; sm[2][w] = vn1; sm[3][w] = vd1; }
    __syncthreads();
    if (threadIdx.x == 0) {
        double a = 0, bq = 0, c = 0, dq = 0;
        for (int i = 0; i < 5; i++) { a += sm[0][i]; bq += sm[1][i]; c += sm[2][i]; dq += sm[3][i]; }
        atomicAdd(&g_acc[0], a);   // N0
        atomicAdd(&g_acc[1], bq);  // D0
        atomicAdd(&g_acc[2], c);   // N1
        atomicAdd(&g_acc[3], dq);  // D1
    }
}

__global__ void k_final(float* out) {
    double loss = fabs(g_acc[0] / (g_acc[1] + 1e-6)) + fabs(g_acc[2] / (g_acc[3] + 1e-6));
    out[0] = (float)(2.0 - loss);
}

extern "C" void kernel_launch(void* const* d_in, const int* in_sizes, int n_in,
                              void* d_out, int out_size) {
    const float* lab = (const float*)d_in[0];   // labels
    const float* inp = (const float*)d_in[1];   // inputs
    float* out = (float*)d_out;

    k_init<<<1, 32>>>();
    k_reduce<<<dim3(512, NB), 256>>>(lab, inp);
    k_genz<<<dim3(NS, NS / ZCH, NB), NS>>>(lab, inp);
    k_convyx_dot<<<dim3(NS, NS / ZCH, NB), NS>>>(lab);
    k_final<<<1, 1>>>(out);
}

// round 4
// speedup vs baseline: 1.9982x; 1.2758x over previous
#include <cuda_runtime.h>
#include <cuda_fp16.h>
#include <math.h>

#define NB   4
#define NS   160
#define NSS  (160*160)
#define NVOX (160*160*160)
#define ZCH  40

#define G_TAPS {0.72614904f,0.83527021f,0.92311635f,0.98019867f,1.0f,\
                0.98019867f,0.92311635f,0.83527021f,0.72614904f}

struct __align__(8) h4 { __half2 a, b; };   // (w0, p*w0) , (w1, (1-p)*w1)

__device__ double g_S[NB * 3];
__device__ double g_acc[4];
__device__ h4 g_bufA[(size_t)NB * NVOX];

__global__ void k_init() {
    int t = threadIdx.x;
    if (t < NB * 3) g_S[t] = 0.0;
    if (t < 4) g_acc[t] = 0.0;
}

__global__ void k_reduce(const float* __restrict__ lab, const float* __restrict__ inp) {
    int b = blockIdx.y;
    const float4* L = (const float4*)(lab + (size_t)b * NVOX);
    const float4* V = (const float4*)(inp + (size_t)b * NVOX);
    double sp = 0.0, sip = 0.0, si = 0.0;
    int n4 = NVOX / 4;
    int stride = blockDim.x * gridDim.x;
    for (int i = blockIdx.x * blockDim.x + threadIdx.x; i < n4; i += stride) {
        float4 p = L[i];
        float4 v = V[i];
        sp  += (double)(p.x + p.y + p.z + p.w);
        sip += (double)(v.x * p.x + v.y * p.y + v.z * p.z + v.w * p.w);
        si  += (double)(v.x + v.y + v.z + v.w);
    }
    #pragma unroll
    for (int o = 16; o > 0; o >>= 1) {
        sp  += __shfl_down_sync(0xffffffffu, sp,  o);
        sip += __shfl_down_sync(0xffffffffu, sip, o);
        si  += __shfl_down_sync(0xffffffffu, si,  o);
    }
    __shared__ double sm[3][8];
    int w = threadIdx.x >> 5, l = threadIdx.x & 31;
    if (l == 0) { sm[0][w] = sp; sm[1][w] = sip; sm[2][w] = si; }
    __syncthreads();
    if (threadIdx.x == 0) {
        double a = 0, c = 0, d = 0;
        int nw = blockDim.x >> 5;
        for (int i = 0; i < nw; i++) { a += sm[0][i]; c += sm[1][i]; d += sm[2][i]; }
        atomicAdd(&g_S[b * 3 + 0], a);
        atomicAdd(&g_S[b * 3 + 1], c);
        atomicAdd(&g_S[b * 3 + 2], d);
    }
}

// Pass 1: generate weights, z-conv in half2, store h4 field. 2 y-rows per block.
__global__ void __launch_bounds__(320) k_genz(const float* __restrict__ lab,
                                              const float* __restrict__ inp) {
    const float G[9] = G_TAPS;
    __half2 G2[9];
    #pragma unroll
    for (int i = 0; i < 9; i++) G2[i] = __float2half2_rn(G[i]);

    int x  = threadIdx.x;              // 0..159
    int y  = blockIdx.x * 2 + threadIdx.y;
    int zc = blockIdx.y;
    int b  = blockIdx.z;

    const double Nv = (double)NVOX;
    double sp  = g_S[b * 3 + 0];
    double sip = g_S[b * 3 + 1];
    double si  = g_S[b * 3 + 2];
    float m0 = (float)((sip / Nv) / (sp / Nv + 1e-5));
    float m1 = (float)(((si - sip) / Nv) / ((Nv - sp) / Nv + 1e-5));

    size_t bbase  = (size_t)b * NVOX;
    int    rowoff = y * NS + x;
    const float* Lp = lab + bbase + rowoff;
    const float* Vp = inp + bbase + rowoff;

    int z0 = zc * ZCH;
    __half2 r01[9], r23[9];
    const __half2 h2z = __float2half2_rn(0.f);

    // prologue: rows z0-4 .. z0+3 into ring[0..7]
    #pragma unroll
    for (int i = 0; i < 8; i++) {
        int z = z0 - 4 + i;
        __half2 a = h2z, c = h2z;
        if (z >= 0) {
            float p = Lp[(size_t)z * NSS];
            float v = Vp[(size_t)z * NSS];
            float d0 = v - m0; float t0 = d0 * d0; float w0 = __expf(-t0 * t0);
            float d1 = v - m1; float t1 = d1 * d1; float w1 = __expf(-t1 * t1);
            a = __floats2half2_rn(w0, p * w0);
            c = __floats2half2_rn(w1, (1.f - p) * w1);
        }
        r01[i] = a; r23[i] = c;
    }

    #pragma unroll 8
    for (int j = 0; j < ZCH; ++j) {
        int zo = z0 + j;
        int zl = zo + 4;
        __half2 a = h2z, c = h2z;
        if (zl < NS) {
            float p = Lp[(size_t)zl * NSS];
            float v = Vp[(size_t)zl * NSS];
            float d0 = v - m0; float t0 = d0 * d0; float w0 = __expf(-t0 * t0);
            float d1 = v - m1; float t1 = d1 * d1; float w1 = __expf(-t1 * t1);
            a = __floats2half2_rn(w0, p * w0);
            c = __floats2half2_rn(w1, (1.f - p) * w1);
        }
        r01[8] = a; r23[8] = c;

        __half2 s01 = __hmul2(G2[0], r01[0]);
        __half2 s23 = __hmul2(G2[0], r23[0]);
        #pragma unroll
        for (int i = 1; i < 9; i++) {
            s01 = __hfma2(G2[i], r01[i], s01);
            s23 = __hfma2(G2[i], r23[i], s23);
        }
        h4 h; h.a = s01; h.b = s23;
        g_bufA[bbase + (size_t)zo * NSS + rowoff] = h;

        #pragma unroll
        for (int i = 0; i < 8; i++) { r01[i] = r01[i + 1]; r23[i] = r23[i + 1]; }
    }
}

// Pass 2 (fused): y-conv (ring, half2) -> smem row (double-buffered, padded)
// -> x-conv (half2) -> dot with class probs -> global reduce.
__global__ void __launch_bounds__(320) k_convyx_dot(const float* __restrict__ lab) {
    const float G[9] = G_TAPS;
    __half2 G2[9];
    #pragma unroll
    for (int i = 0; i < 9; i++) G2[i] = __float2half2_rn(G[i]);

    int x  = threadIdx.x;              // 0..159
    int ty = threadIdx.y;              // 0..1
    int z  = blockIdx.x * 2 + ty;
    int yc = blockIdx.y;
    int b  = blockIdx.z;

    __shared__ h4 rowbuf[2][2][NS + 8];   // [ty][buf][padded x]
    const __half2 h2z = __float2half2_rn(0.f);

    // zero the halo pads once
    if (x < 4) {
        h4 zz; zz.a = h2z; zz.b = h2z;
        rowbuf[ty][0][x] = zz;            rowbuf[ty][1][x] = zz;
        rowbuf[ty][0][NS + 4 + x] = zz;   rowbuf[ty][1][NS + 4 + x] = zz;
    }
    __syncthreads();

    int y0 = yc * ZCH;
    size_t pbase = (size_t)b * NVOX + (size_t)z * NSS;
    const h4* src = g_bufA + pbase + x;
    const float* Lp = lab + pbase + x;

    __half2 r01[9], r23[9];
    // prologue: rows y0-4 .. y0+3
    #pragma unroll
    for (int i = 0; i < 8; i++) {
        int y = y0 - 4 + i;
        __half2 a = h2z, c = h2z;
        if (y >= 0) { h4 h = src[(size_t)y * NS]; a = h.a; c = h.b; }
        r01[i] = a; r23[i] = c;
    }

    float n0 = 0.f, d0 = 0.f, n1 = 0.f, d1 = 0.f;

    #pragma unroll 8
    for (int j = 0; j < ZCH; ++j) {
        int yo = y0 + j;
        int yl = yo + 4;
        __half2 a = h2z, c = h2z;
        if (yl < NS) { h4 h = src[(size_t)yl * NS]; a = h.a; c = h.b; }
        r01[8] = a; r23[8] = c;

        __half2 s01 = __hmul2(G2[0], r01[0]);
        __half2 s23 = __hmul2(G2[0], r23[0]);
        #pragma unroll
        for (int i = 1; i < 9; i++) {
            s01 = __hfma2(G2[i], r01[i], s01);
            s23 = __hfma2(G2[i], r23[i], s23);
        }
        int bf = j & 1;
        h4 hv; hv.a = s01; hv.b = s23;
        rowbuf[ty][bf][x + 4] = hv;
        __syncthreads();

        h4 t0 = rowbuf[ty][bf][x];
        __half2 c01 = __hmul2(G2[0], t0.a);
        __half2 c23 = __hmul2(G2[0], t0.b);
        #pragma unroll
        for (int i = 1; i < 9; i++) {
            h4 t = rowbuf[ty][bf][x + i];
            c01 = __hfma2(G2[i], t.a, c01);
            c23 = __hfma2(G2[i], t.b, c23);
        }

        float2 fa = __half22float2(c01);
        float2 fb = __half22float2(c23);
        float p = Lp[(size_t)yo * NS];
        d0 += p * fa.x;
        n0 += p * fa.y;
        d1 += (1.f - p) * fb.x;
        n1 += (1.f - p) * fb.y;

        #pragma unroll
        for (int i = 0; i < 8; i++) { r01[i] = r01[i + 1]; r23[i] = r23[i + 1]; }
    }

    double vn0 = n0, vd0 = d0, vn1 = n1, vd1 = d1;
    #pragma unroll
    for (int o = 16; o > 0; o >>= 1) {
        vn0 += __shfl_down_sync(0xffffffffu, vn0, o);
        vd0 += __shfl_down_sync(0xffffffffu, vd0, o);
        vn1 += __shfl_down_sync(0xffffffffu, vn1, o);
        vd1 += __shfl_down_sync(0xffffffffu, vd1, o);
    }
    __shared__ double sm[4][10];
    int tid = threadIdx.y * 160 + threadIdx.x;
    int w = tid >> 5, l = tid & 31;
    if (l == 0) { sm[0][w] = vn0; sm[1][w] = vd0; sm[2][w] = vn1; sm[3][w] = vd1; }
    __syncthreads();
    if (tid == 0) {
        double aa = 0, bb = 0, cc = 0, dd = 0;
        for (int i = 0; i < 10; i++) { aa += sm[0][i]; bb += sm[1][i]; cc += sm[2][i]; dd += sm[3][i]; }
        atomicAdd(&g_acc[0], aa);
        atomicAdd(&g_acc[1], bb);
        atomicAdd(&g_acc[2], cc);
        atomicAdd(&g_acc[3], dd);
    }
}

__global__ void k_final(float* out) {
    double loss = fabs(g_acc[0] / (g_acc[1] + 1e-6)) + fabs(g_acc[2] / (g_acc[3] + 1e-6));
    out[0] = (float)(2.0 - loss);
}

extern "C" void kernel_launch(void* const* d_in, const int* in_sizes, int n_in,
                              void* d_out, int out_size) {
    const float* lab = (const float*)d_in[0];
    const float* inp = (const float*)d_in[1];
    float* out = (float*)d_out;

    k_init<<<1, 32>>>();
    k_reduce<<<dim3(512, NB), 256>>>(lab, inp);
    k_genz<<<dim3(NS / 2, NS / ZCH, NB), dim3(NS, 2)>>>(lab, inp);
    k_convyx_dot<<<dim3(NS / 2, NS / ZCH, NB), dim3(NS, 2)>>>(lab);
    k_final<<<1, 1>>>(out);
}

// round 6
// speedup vs baseline: 2.4907x; 1.2465x over previous
#include <cuda_runtime.h>
#include <cuda_fp16.h>
#include <math.h>

#define NB   4
#define NS   160
#define NSS  (160*160)
#define NVOX (160*160*160)
#define ZCH  40

// 1D gaussian taps, sigma=5, radius=4: exp(-i^2/50)
#define G_TAPS {0.72614904f,0.83527021f,0.92311635f,0.98019867f,1.0f,\
                0.98019867f,0.92311635f,0.83527021f,0.72614904f}

__device__ double g_S[NB * 3];
__device__ double g_acc[4];
__device__ __half2 g_q[(size_t)NB * NVOX / 2];   // K_z-convolved p (then y,x in pass 2)

// conv-of-ones along one axis at index i (zero padding): closed form
__device__ __forceinline__ float cfun(int i) {
    const float H[5] = {1.0f, 1.98019867f, 2.90331502f, 3.73858523f, 4.46473427f};
    int a = i < 4 ? i : 4;
    int c = (159 - i) < 4 ? (159 - i) : 4;
    return H[a] + H[c] - 1.0f;
}

__global__ void k_init() {
    int t = threadIdx.x;
    if (t < NB * 3) g_S[t] = 0.0;
    if (t < 4) g_acc[t] = 0.0;
}

// Fused: blockIdx.y==4 -> global reduction (means); else z-conv of p -> g_q (fp16).
// The two roles are independent and overlap in one launch.
__global__ void __launch_bounds__(320) k_AB(const float* __restrict__ lab,
                                            const float* __restrict__ inp) {
    int b = blockIdx.z;
    if (blockIdx.y == 4) {
        // ---- reduction role ----
        int tid = threadIdx.y * 80 + threadIdx.x;
        const float4* L = (const float4*)(lab + (size_t)b * NVOX);
        const float4* V = (const float4*)(inp + (size_t)b * NVOX);
        double sp = 0.0, sip = 0.0, si = 0.0;
        int n4 = NVOX / 4;
        for (int i = blockIdx.x * 320 + tid; i < n4; i += 40 * 320) {
            float4 p = L[i];
            float4 v = V[i];
            sp  += (double)(p.x + p.y + p.z + p.w);
            sip += (double)(v.x * p.x + v.y * p.y + v.z * p.z + v.w * p.w);
            si  += (double)(v.x + v.y + v.z + v.w);
        }
        #pragma unroll
        for (int o = 16; o > 0; o >>= 1) {
            sp  += __shfl_down_sync(0xffffffffu, sp,  o);
            sip += __shfl_down_sync(0xffffffffu, sip, o);
            si  += __shfl_down_sync(0xffffffffu, si,  o);
        }
        __shared__ double sm[3][10];
        int w = tid >> 5, l = tid & 31;
        if (l == 0) { sm[0][w] = sp; sm[1][w] = sip; sm[2][w] = si; }
        __syncthreads();
        if (tid == 0) {
            double a = 0, c = 0, d = 0;
            for (int i = 0; i < 10; i++) { a += sm[0][i]; c += sm[1][i]; d += sm[2][i]; }
            atomicAdd(&g_S[b * 3 + 0], a);
            atomicAdd(&g_S[b * 3 + 1], c);
            atomicAdd(&g_S[b * 3 + 2], d);
        }
    } else {
        // ---- z-conv of p role (single channel, 2 x-values per thread) ----
        const float G[9] = G_TAPS;
        __half2 G2[9];
        #pragma unroll
        for (int i = 0; i < 9; i++) G2[i] = __float2half2_rn(G[i]);

        int hx = threadIdx.x;                       // x pair: 2hx, 2hx+1
        int y  = blockIdx.x * 4 + threadIdx.y;
        int z0 = blockIdx.y * ZCH;

        const float2* Lp = (const float2*)(lab + (size_t)b * NVOX + (size_t)y * NS) + hx;
        __half2* Q = g_q + ((size_t)b * NVOX + (size_t)y * NS) / 2 + hx;
        const __half2 h2z = __float2half2_rn(0.f);

        __half2 ring[9];
        #pragma unroll
        for (int i = 0; i < 8; i++) {
            int z = z0 - 4 + i;
            __half2 v = h2z;
            if (z >= 0) { float2 f = Lp[(size_t)z * (NSS / 2)]; v = __floats2half2_rn(f.x, f.y); }
            ring[i] = v;
        }
        #pragma unroll 8
        for (int j = 0; j < ZCH; ++j) {
            int zl = z0 + j + 4;
            __half2 v = h2z;
            if (zl < NS) { float2 f = Lp[(size_t)zl * (NSS / 2)]; v = __floats2half2_rn(f.x, f.y); }
            ring[8] = v;
            __half2 s = __hmul2(G2[0], ring[0]);
            #pragma unroll
            for (int i = 1; i < 9; i++) s = __hfma2(G2[i], ring[i], s);
            Q[(size_t)(z0 + j) * (NSS / 2)] = s;
            #pragma unroll
            for (int i = 0; i < 8; i++) ring[i] = ring[i + 1];
        }
    }
}

// Pass 2: y-conv (ring) + x-conv (smem, paired taps) on q, then pointwise
// weights + all four dot products. 4 rows per barrier phase.
__global__ void __launch_bounds__(320) k_C(const float* __restrict__ lab,
                                           const float* __restrict__ inp) {
    const float G[9] = G_TAPS;
    __half2 G2[9];
    #pragma unroll
    for (int i = 0; i < 9; i++) G2[i] = __float2half2_rn(G[i]);
    // paired taps for even/odd x outputs from aligned half2 loads
    __half2 TE[5], TO[5];
    TE[0] = __floats2half2_rn(G[0], G[1]); TE[1] = __floats2half2_rn(G[2], G[3]);
    TE[2] = __floats2half2_rn(G[4], G[5]); TE[3] = __floats2half2_rn(G[6], G[7]);
    TE[4] = __floats2half2_rn(G[8], 0.f);
    TO[0] = __floats2half2_rn(0.f, G[0]);  TO[1] = __floats2half2_rn(G[1], G[2]);
    TO[2] = __floats2half2_rn(G[3], G[4]); TO[3] = __floats2half2_rn(G[5], G[6]);
    TO[4] = __floats2half2_rn(G[7], G[8]);

    int hx = threadIdx.x;          // 0..79
    int tz = threadIdx.y;          // 0..3
    int z  = blockIdx.x * 4 + tz;
    int y0 = blockIdx.y * ZCH;
    int b  = blockIdx.z;

    const double Nv = (double)NVOX;
    double sp  = g_S[b * 3 + 0];
    double sip = g_S[b * 3 + 1];
    double si  = g_S[b * 3 + 2];
    float m0 = (float)((sip / Nv) / (sp / Nv + 1e-5));
    float m1 = (float)(((si - sip) / Nv) / ((Nv - sp) / Nv + 1e-5));

    float cz  = cfun(z);
    float ce  = cfun(2 * hx) * cz;       // C factor for even x
    float co  = cfun(2 * hx + 1) * cz;   // odd x

    __shared__ __half2 srow[4][4][84];   // [tz][row-in-batch][hx+2], pads at 0,1,82,83
    const __half2 h2z = __float2half2_rn(0.f);
    if (hx < 2) {
        #pragma unroll
        for (int jj = 0; jj < 4; jj++) { srow[tz][jj][hx] = h2z; srow[tz][jj][82 + hx] = h2z; }
    }

    size_t pbase = (size_t)b * NVOX + (size_t)z * NSS;
    const __half2* Q = g_q + pbase / 2 + hx;
    const float2* Lp = (const float2*)(lab + pbase) + hx;
    const float2* Vp = (const float2*)(inp + pbase) + hx;

    __half2 ring[9];
    #pragma unroll
    for (int i = 0; i < 8; i++) {
        int y = y0 - 4 + i;
        ring[i] = (y >= 0) ? Q[(size_t)y * 80] : h2z;
    }

    float aD0 = 0.f, aN0 = 0.f, aD1 = 0.f, aN1 = 0.f;

    for (int yb = 0; yb < ZCH / 4; ++yb) {
        #pragma unroll
        for (int jj = 0; jj < 4; jj++) {
            int yl = y0 + yb * 4 + jj + 4;
            ring[8] = (yl < NS) ? Q[(size_t)yl * 80] : h2z;
            __half2 s = __hmul2(G2[0], ring[0]);
            #pragma unroll
            for (int i = 1; i < 9; i++) s = __hfma2(G2[i], ring[i], s);
            srow[tz][jj][hx + 2] = s;
            #pragma unroll
            for (int i = 0; i < 8; i++) ring[i] = ring[i + 1];
        }
        __syncthreads();
        #pragma unroll
        for (int jj = 0; jj < 4; jj++) {
            int y = y0 + yb * 4 + jj;
            __half2 h0 = srow[tz][jj][hx + 0];
            __half2 h1 = srow[tz][jj][hx + 1];
            __half2 h2 = srow[tz][jj][hx + 2];
            __half2 h3 = srow[tz][jj][hx + 3];
            __half2 h4 = srow[tz][jj][hx + 4];
            __half2 se = __hmul2(TE[0], h0);
            se = __hfma2(TE[1], h1, se); se = __hfma2(TE[2], h2, se);
            se = __hfma2(TE[3], h3, se); se = __hfma2(TE[4], h4, se);
            __half2 so = __hmul2(TO[0], h0);
            so = __hfma2(TO[1], h1, so); so = __hfma2(TO[2], h2, so);
            so = __hfma2(TO[3], h3, so); so = __hfma2(TO[4], h4, so);
            float2 fe = __half22float2(se);
            float2 fo = __half22float2(so);
            float qe = fe.x + fe.y;          // q at x=2hx
            float qo = fo.x + fo.y;          // q at x=2hx+1
            float cy  = cfun(y);
            float qce = ce * cy - qe;        // (K*(1-p)) even
            float qco = co * cy - qo;        // odd

            float2 P  = Lp[(size_t)y * 80];
            float2 Vv = Vp[(size_t)y * 80];
            // even lane
            {
                float p = P.x, v = Vv.x;
                float d0 = v - m0; float u0 = d0 * d0; float w0 = __expf(-u0 * u0);
                float d1 = v - m1; float u1 = d1 * d1; float w1 = __expf(-u1 * u1);
                aD0 += w0 * qe;  aN0 += p * w0 * qe;
                aD1 += w1 * qce; aN1 += (1.f - p) * w1 * qce;
            }
            // odd lane
            {
                float p = P.y, v = Vv.y;
                float d0 = v - m0; float u0 = d0 * d0; float w0 = __expf(-u0 * u0);
                float d1 = v - m1; float u1 = d1 * d1; float w1 = __expf(-u1 * u1);
                aD0 += w0 * qo;  aN0 += p * w0 * qo;
                aD1 += w1 * qco; aN1 += (1.f - p) * w1 * qco;
            }
        }
        __syncthreads();
    }

    double vn0 = aN0, vd0 = aD0, vn1 = aN1, vd1 = aD1;
    #pragma unroll
    for (int o = 16; o > 0; o >>= 1) {
        vn0 += __shfl_down_sync(0xffffffffu, vn0, o);
        vd0 += __shfl_down_sync(0xffffffffu, vd0, o);
        vn1 += __shfl_down_sync(0xffffffffu, vn1, o);
        vd1 += __shfl_down_sync(0xffffffffu, vd1, o);
    }
    __shared__ double sm[4][10];
    int tid = tz * 80 + hx;
    int w = tid >> 5, l = tid & 31;
    if (l == 0) { sm[0][w] = vn0; sm[1][w] = vd0; sm[2][w] = vn1; sm[3][w] = vd1; }
    __syncthreads();
    if (tid == 0) {
        double aa = 0, bb = 0, cc = 0, dd = 0;
        for (int i = 0; i < 10; i++) { aa += sm[0][i]; bb += sm[1][i]; cc += sm[2][i]; dd += sm[3][i]; }
        atomicAdd(&g_acc[0], aa);
        atomicAdd(&g_acc[1], bb);
        atomicAdd(&g_acc[2], cc);
        atomicAdd(&g_acc[3], dd);
    }
}

__global__ void k_final(float* out) {
    double loss = fabs(g_acc[0] / (g_acc[1] + 1e-6)) + fabs(g_acc[2] / (g_acc[3] + 1e-6));
    out[0] = (float)(2.0 - loss);
}

extern "C" void kernel_launch(void* const* d_in, const int* in_sizes, int n_in,
                              void* d_out, int out_size) {
    const float* lab = (const float*)d_in[0];
    const float* inp = (const float*)d_in[1];
    float* out = (float*)d_out;

    k_init<<<1, 32>>>();
    k_AB<<<dim3(40, 5, NB), dim3(80, 4)>>>(lab, inp);   // reduce ∥ z-conv(p)
    k_C<<<dim3(40, 4, NB), dim3(80, 4)>>>(lab, inp);    // y/x-conv + weights + dots
    k_final<<<1, 1>>>(out);
}

// round 7
// speedup vs baseline: 3.9911x; 1.6024x over previous
#include <cuda_runtime.h>
#include <cuda_fp16.h>
#include <math.h>

#define NB   4
#define NS   160
#define NSS  (160*160)
#define NVOX (160*160*160)
#define ZCH  40
#define NBLK2 640   // k_C total blocks: 40*4*NB

// 1D gaussian taps, sigma=5, radius=4: exp(-i^2/50)
#define G_TAPS {0.72614904f,0.83527021f,0.92311635f,0.98019867f,1.0f,\
                0.98019867f,0.92311635f,0.83527021f,0.72614904f}

__device__ __half2 g_q[(size_t)NB * NVOX / 2];  // K_z * p
__device__ double g_p1[NB * 160 * 3];           // pass-1 per-block (sp, sip, si)
__device__ double g_p2[NBLK2 * 4];              // pass-2 per-block (N0,D0,N1,D1)
__device__ unsigned g_cnt = 0;                  // self-resetting finalize counter

// conv-of-ones along one axis at index i (zero padding): closed form
__device__ __forceinline__ float cfun(int i) {
    const float H[5] = {1.0f, 1.98019867f, 2.90331502f, 3.73858523f, 4.46473427f};
    int a = i < 4 ? i : 4;
    int c = (159 - i) < 4 ? (159 - i) : 4;
    return H[a] + H[c] - 1.0f;
}

// Pass 1: z-conv of p -> g_q (fp16), with the global sums (p, v*p, v) fused
// into the same streaming loop (ring[4] is p at the output voxel).
__global__ void __launch_bounds__(320) k_A(const float* __restrict__ lab,
                                           const float* __restrict__ inp) {
    const float G[9] = G_TAPS;
    __half2 G2[9];
    #pragma unroll
    for (int i = 0; i < 9; i++) G2[i] = __float2half2_rn(G[i]);

    int hx = threadIdx.x;                 // 0..79 (x pair)
    int ty = threadIdx.y;                 // 0..3
    int y  = blockIdx.x * 4 + ty;
    int z0 = blockIdx.y * ZCH;
    int b  = blockIdx.z;

    const float2* Lp = (const float2*)(lab + (size_t)b * NVOX + (size_t)y * NS) + hx;
    const float2* Vp = (const float2*)(inp + (size_t)b * NVOX + (size_t)y * NS) + hx;
    __half2* Q = g_q + ((size_t)b * NVOX + (size_t)y * NS) / 2 + hx;
    const __half2 h2z = __float2half2_rn(0.f);

    __half2 ring[9];
    #pragma unroll
    for (int i = 0; i < 8; i++) {
        int z = z0 - 4 + i;
        __half2 v = h2z;
        if (z >= 0) { float2 f = Lp[(size_t)z * (NSS / 2)]; v = __floats2half2_rn(f.x, f.y); }
        ring[i] = v;
    }

    float sp = 0.f, sip = 0.f, si = 0.f;

    #pragma unroll 8
    for (int j = 0; j < ZCH; ++j) {
        int zl = z0 + j + 4;
        __half2 v = h2z;
        if (zl < NS) { float2 f = Lp[(size_t)zl * (NSS / 2)]; v = __floats2half2_rn(f.x, f.y); }
        ring[8] = v;

        // fused global sums: ring[4] holds p at z0+j
        float2 vc = Vp[(size_t)(z0 + j) * (NSS / 2)];
        float2 pc = __half22float2(ring[4]);
        sp  += pc.x + pc.y;
        sip += vc.x * pc.x + vc.y * pc.y;
        si  += vc.x + vc.y;

        __half2 s = __hmul2(G2[0], ring[0]);
        #pragma unroll
        for (int i = 1; i < 9; i++) s = __hfma2(G2[i], ring[i], s);
        Q[(size_t)(z0 + j) * (NSS / 2)] = s;
        #pragma unroll
        for (int i = 0; i < 8; i++) ring[i] = ring[i + 1];
    }

    // block-reduce the three sums (double), write partial slot (no atomics)
    double a = sp, c = sip, d = si;
    #pragma unroll
    for (int o = 16; o > 0; o >>= 1) {
        a += __shfl_down_sync(0xffffffffu, a, o);
        c += __shfl_down_sync(0xffffffffu, c, o);
        d += __shfl_down_sync(0xffffffffu, d, o);
    }
    __shared__ double sm[3][10];
    int tid = ty * 80 + hx;
    int w = tid >> 5, l = tid & 31;
    if (l == 0) { sm[0][w] = a; sm[1][w] = c; sm[2][w] = d; }
    __syncthreads();
    if (tid == 0) {
        double aa = 0, cc = 0, dd = 0;
        for (int i = 0; i < 10; i++) { aa += sm[0][i]; cc += sm[1][i]; dd += sm[2][i]; }
        int pb = ((b * 4 + blockIdx.y) * 40 + blockIdx.x) * 3;
        g_p1[pb + 0] = aa;
        g_p1[pb + 1] = cc;
        g_p1[pb + 2] = dd;
    }
}

// Pass 2: means from partials, y-conv (ring) + x-conv (smem, paired taps) on q,
// pointwise weights + four dots, partials + last-block finalize.
__global__ void __launch_bounds__(320) k_C(const float* __restrict__ lab,
                                           const float* __restrict__ inp,
                                           float* __restrict__ out) {
    const float G[9] = G_TAPS;
    __half2 G2[9];
    #pragma unroll
    for (int i = 0; i < 9; i++) G2[i] = __float2half2_rn(G[i]);
    __half2 TE[5], TO[5];
    TE[0] = __floats2half2_rn(G[0], G[1]); TE[1] = __floats2half2_rn(G[2], G[3]);
    TE[2] = __floats2half2_rn(G[4], G[5]); TE[3] = __floats2half2_rn(G[6], G[7]);
    TE[4] = __floats2half2_rn(G[8], 0.f);
    TO[0] = __floats2half2_rn(0.f, G[0]);  TO[1] = __floats2half2_rn(G[1], G[2]);
    TO[2] = __floats2half2_rn(G[3], G[4]); TO[3] = __floats2half2_rn(G[5], G[6]);
    TO[4] = __floats2half2_rn(G[7], G[8]);

    int hx = threadIdx.x;          // 0..79
    int tz = threadIdx.y;          // 0..3
    int z  = blockIdx.x * 4 + tz;
    int y0 = blockIdx.y * ZCH;
    int b  = blockIdx.z;
    int tid = tz * 80 + hx;

    // means from pass-1 partials (warp 0 sums 160 slots, broadcasts)
    __shared__ float s_m[2];
    if (tid < 32) {
        double a = 0, c = 0, d = 0;
        for (int i = tid; i < 160; i += 32) {
            int base = (b * 160 + i) * 3;
            a += g_p1[base + 0]; c += g_p1[base + 1]; d += g_p1[base + 2];
        }
        #pragma unroll
        for (int o = 16; o > 0; o >>= 1) {
            a += __shfl_down_sync(0xffffffffu, a, o);
            c += __shfl_down_sync(0xffffffffu, c, o);
            d += __shfl_down_sync(0xffffffffu, d, o);
        }
        if (tid == 0) {
            const double Nv = (double)NVOX;
            s_m[0] = (float)((c / Nv) / (a / Nv + 1e-5));
            s_m[1] = (float)(((d - c) / Nv) / ((Nv - a) / Nv + 1e-5));
        }
    }

    __shared__ __half2 srow[4][4][84];   // [tz][row][hx+2], pads at 0,1,82,83
    const __half2 h2z = __float2half2_rn(0.f);
    if (hx < 2) {
        #pragma unroll
        for (int jj = 0; jj < 4; jj++) { srow[tz][jj][hx] = h2z; srow[tz][jj][82 + hx] = h2z; }
    }
    __syncthreads();
    float m0 = s_m[0], m1 = s_m[1];

    float cz = cfun(z);
    float ce = cfun(2 * hx) * cz;
    float co = cfun(2 * hx + 1) * cz;

    size_t pbase = (size_t)b * NVOX + (size_t)z * NSS;
    const __half2* Q = g_q + pbase / 2 + hx;
    const float2* Lp = (const float2*)(lab + pbase) + hx;
    const float2* Vp = (const float2*)(inp + pbase) + hx;

    __half2 ring[9];
    #pragma unroll
    for (int i = 0; i < 8; i++) {
        int y = y0 - 4 + i;
        ring[i] = (y >= 0) ? Q[(size_t)y * 80] : h2z;
    }

    float aD0 = 0.f, aN0 = 0.f, aD1 = 0.f, aN1 = 0.f;

    for (int yb = 0; yb < ZCH / 4; ++yb) {
        #pragma unroll
        for (int jj = 0; jj < 4; jj++) {
            int yl = y0 + yb * 4 + jj + 4;
            ring[8] = (yl < NS) ? Q[(size_t)yl * 80] : h2z;
            __half2 s = __hmul2(G2[0], ring[0]);
            #pragma unroll
            for (int i = 1; i < 9; i++) s = __hfma2(G2[i], ring[i], s);
            srow[tz][jj][hx + 2] = s;
            #pragma unroll
            for (int i = 0; i < 8; i++) ring[i] = ring[i + 1];
        }
        __syncthreads();
        #pragma unroll
        for (int jj = 0; jj < 4; jj++) {
            int y = y0 + yb * 4 + jj;
            __half2 h0 = srow[tz][jj][hx + 0];
            __half2 h1 = srow[tz][jj][hx + 1];
            __half2 h2 = srow[tz][jj][hx + 2];
            __half2 h3 = srow[tz][jj][hx + 3];
            __half2 h4 = srow[tz][jj][hx + 4];
            __half2 se = __hmul2(TE[0], h0);
            se = __hfma2(TE[1], h1, se); se = __hfma2(TE[2], h2, se);
            se = __hfma2(TE[3], h3, se); se = __hfma2(TE[4], h4, se);
            __half2 so = __hmul2(TO[0], h0);
            so = __hfma2(TO[1], h1, so); so = __hfma2(TO[2], h2, so);
            so = __hfma2(TO[3], h3, so); so = __hfma2(TO[4], h4, so);
            float2 fe = __half22float2(se);
            float2 fo = __half22float2(so);
            float qe = fe.x + fe.y;
            float qo = fo.x + fo.y;
            float cy = cfun(y);
            float qce = ce * cy - qe;
            float qco = co * cy - qo;

            float2 P  = Lp[(size_t)y * 80];
            float2 Vv = Vp[(size_t)y * 80];
            {
                float p = P.x, v = Vv.x;
                float d0 = v - m0; float u0 = d0 * d0; float w0 = __expf(-u0 * u0);
                float d1 = v - m1; float u1 = d1 * d1; float w1 = __expf(-u1 * u1);
                aD0 += w0 * qe;  aN0 += p * w0 * qe;
                aD1 += w1 * qce; aN1 += (1.f - p) * w1 * qce;
            }
            {
                float p = P.y, v = Vv.y;
                float d0 = v - m0; float u0 = d0 * d0; float w0 = __expf(-u0 * u0);
                float d1 = v - m1; float u1 = d1 * d1; float w1 = __expf(-u1 * u1);
                aD0 += w0 * qo;  aN0 += p * w0 * qo;
                aD1 += w1 * qco; aN1 += (1.f - p) * w1 * qco;
            }
        }
        __syncthreads();
    }

    // block-reduce four accumulators, write partial, last block finalizes
    double vn0 = aN0, vd0 = aD0, vn1 = aN1, vd1 = aD1;
    #pragma unroll
    for (int o = 16; o > 0; o >>= 1) {
        vn0 += __shfl_down_sync(0xffffffffu, vn0, o);
        vd0 += __shfl_down_sync(0xffffffffu, vd0, o);
        vn1 += __shfl_down_sync(0xffffffffu, vn1, o);
        vd1 += __shfl_down_sync(0xffffffffu, vd1, o);
    }
    __shared__ double sm[4][10];
    int w = tid >> 5, l = tid & 31;
    if (l == 0) { sm[0][w] = vn0; sm[1][w] = vd0; sm[2][w] = vn1; sm[3][w] = vd1; }
    __syncthreads();

    __shared__ int s_last;
    int bid = (b * 4 + blockIdx.y) * 40 + blockIdx.x;
    if (tid == 0) {
        double aa = 0, bb = 0, cc = 0, dd = 0;
        for (int i = 0; i < 10; i++) { aa += sm[0][i]; bb += sm[1][i]; cc += sm[2][i]; dd += sm[3][i]; }
        g_p2[bid * 4 + 0] = aa;
        g_p2[bid * 4 + 1] = bb;
        g_p2[bid * 4 + 2] = cc;
        g_p2[bid * 4 + 3] = dd;
        __threadfence();
        unsigned t = atomicAdd(&g_cnt, 1);
        s_last = (t == NBLK2 - 1);
    }
    __syncthreads();
    if (s_last) {
        double s0 = 0, s1 = 0, s2 = 0, s3 = 0;
        for (int i = tid; i < NBLK2; i += 320) {
            s0 += g_p2[i * 4 + 0];
            s1 += g_p2[i * 4 + 1];
            s2 += g_p2[i * 4 + 2];
            s3 += g_p2[i * 4 + 3];
        }
        #pragma unroll
        for (int o = 16; o > 0; o >>= 1) {
            s0 += __shfl_down_sync(0xffffffffu, s0, o);
            s1 += __shfl_down_sync(0xffffffffu, s1, o);
            s2 += __shfl_down_sync(0xffffffffu, s2, o);
            s3 += __shfl_down_sync(0xffffffffu, s3, o);
        }
        if (l == 0) { sm[0][w] = s0; sm[1][w] = s1; sm[2][w] = s2; sm[3][w] = s3; }
        __syncthreads();
        if (tid == 0) {
            double aa = 0, bb = 0, cc = 0, dd = 0;
            for (int i = 0; i < 10; i++) { aa += sm[0][i]; bb += sm[1][i]; cc += sm[2][i]; dd += sm[3][i]; }
            double loss = fabs(aa / (bb + 1e-6)) + fabs(cc / (dd + 1e-6));
            out[0] = (float)(2.0 - loss);
            g_cnt = 0;   // reset for next graph replay
        }
    }
}

extern "C" void kernel_launch(void* const* d_in, const int* in_sizes, int n_in,
                              void* d_out, int out_size) {
    const float* lab = (const float*)d_in[0];
    const float* inp = (const float*)d_in[1];
    float* out = (float*)d_out;

    k_A<<<dim3(40, 4, NB), dim3(80, 4)>>>(lab, inp);        // z-conv(p) + fused sums
    k_C<<<dim3(40, 4, NB), dim3(80, 4)>>>(lab, inp, out);   // y/x-conv + weights + dots + finalize
}

// round 9
// speedup vs baseline: 4.9770x; 1.2470x over previous
#include <cuda_runtime.h>
#include <cuda_fp16.h>
#include <math.h>

#define NB   4
#define NS   160
#define NSS  (160*160)
#define NVOX (160*160*160)
#define ZCH  40
#define NBLK2 320   // pass-2 blocks: 20*4*NB

// 1D gaussian taps, sigma=5, radius=4: exp(-i^2/50)
#define G_TAPS {0.72614904f,0.83527021f,0.92311635f,0.98019867f,1.0f,\
                0.98019867f,0.92311635f,0.83527021f,0.72614904f}

__device__ __forceinline__ unsigned h2_as_u32(__half2 h) {
    return *reinterpret_cast<unsigned*>(&h);
}
__device__ __forceinline__ __half2 u32_as_h2(unsigned u) {
    return *reinterpret_cast<__half2*>(&u);
}

__device__ __half2 g_q[(size_t)NB * NVOX / 2];   // (K_x * K_z * p), half2 per x-pair
__device__ __half2 g_pv[(size_t)NB * NVOX];      // per voxel (p, v) packed fp16
__device__ double g_p1[NB * 160 * 3];            // pass-1 per-block (sp, sip, si)
__device__ double g_p2[NBLK2 * 4];               // pass-2 per-block (N0,D0,N1,D1)
__device__ unsigned g_cnt = 0;                   // self-resetting finalize counter

// conv-of-ones along one axis (zero padding): closed form
__device__ __forceinline__ float cfun(int i) {
    const float H[5] = {1.0f, 1.98019867f, 2.90331502f, 3.73858523f, 4.46473427f};
    int a = i < 4 ? i : 4;
    int c = (159 - i) < 4 ? (159 - i) : 4;
    return H[a] + H[c] - 1.0f;
}

// Pass 1: stream lab/inp along z. Per z-step: fused mean sums, pack+store (p,v),
// z-conv (ring), smem row, x-conv (paired taps) -> store zx-convolved q (fp16).
__global__ void __launch_bounds__(320) k_A(const float* __restrict__ lab,
                                           const float* __restrict__ inp) {
    const float G[9] = G_TAPS;
    __half2 G2[9];
    #pragma unroll
    for (int i = 0; i < 9; i++) G2[i] = __float2half2_rn(G[i]);
    __half2 TE[5], TO[5];
    TE[0] = __floats2half2_rn(G[0], G[1]); TE[1] = __floats2half2_rn(G[2], G[3]);
    TE[2] = __floats2half2_rn(G[4], G[5]); TE[3] = __floats2half2_rn(G[6], G[7]);
    TE[4] = __floats2half2_rn(G[8], 0.f);
    TO[0] = __floats2half2_rn(0.f, G[0]);  TO[1] = __floats2half2_rn(G[1], G[2]);
    TO[2] = __floats2half2_rn(G[3], G[4]); TO[3] = __floats2half2_rn(G[5], G[6]);
    TO[4] = __floats2half2_rn(G[7], G[8]);

    int hx = threadIdx.x;                 // 0..79 (x pair)
    int ty = threadIdx.y;                 // 0..3
    int y  = blockIdx.x * 4 + ty;
    int z0 = blockIdx.y * ZCH;
    int b  = blockIdx.z;

    size_t rowbase = (size_t)b * NVOX + (size_t)y * NS;   // voxel index of (b,*,y,0)
    const float2* Lp = (const float2*)(lab + rowbase) + hx;
    const float2* Vp = (const float2*)(inp + rowbase) + hx;
    uint2* PV = (uint2*)g_pv + rowbase / 4;               // +z*NSS/4 + hx per step
    __half2* Q = g_q + rowbase / 2 + hx;                  // +z*NSS/2 per step

    __shared__ __half2 srow[4][2][84];    // [ty][buf][hx+2], pads at 0,1,82,83
    const __half2 h2z = __float2half2_rn(0.f);
    if (hx < 2) {
        srow[ty][0][hx] = h2z;       srow[ty][1][hx] = h2z;
        srow[ty][0][82 + hx] = h2z;  srow[ty][1][82 + hx] = h2z;
    }

    __half2 ring[9];
    #pragma unroll
    for (int i = 0; i < 8; i++) {
        int z = z0 - 4 + i;
        __half2 v = h2z;
        if (z >= 0) { float2 f = Lp[(size_t)z * (NSS / 2)]; v = __floats2half2_rn(f.x, f.y); }
        ring[i] = v;
    }

    float sp = 0.f, sip = 0.f, si = 0.f;

    #pragma unroll 8
    for (int j = 0; j < ZCH; ++j) {
        int z = z0 + j;
        int zl = z + 4;
        __half2 v = h2z;
        if (zl < NS) { float2 f = Lp[(size_t)zl * (NSS / 2)]; v = __floats2half2_rn(f.x, f.y); }
        ring[8] = v;

        // fused sums + (p,v) pack at current z (ring[4] is p here, fp16)
        float2 vc = Vp[(size_t)z * (NSS / 2)];
        float2 pc = __half22float2(ring[4]);
        sp  += pc.x + pc.y;
        sip += vc.x * pc.x + vc.y * pc.y;
        si  += vc.x + vc.y;
        __half2 pv0 = __halves2half2(__low2half(ring[4]),  __float2half_rn(vc.x));
        __half2 pv1 = __halves2half2(__high2half(ring[4]), __float2half_rn(vc.y));
        uint2 pvw;
        pvw.x = h2_as_u32(pv0);
        pvw.y = h2_as_u32(pv1);
        PV[(size_t)z * (NSS / 4) + hx] = pvw;

        // z-conv
        __half2 s = __hmul2(G2[0], ring[0]);
        #pragma unroll
        for (int i = 1; i < 9; i++) s = __hfma2(G2[i], ring[i], s);

        int bf = j & 1;
        srow[ty][bf][hx + 2] = s;
        __syncthreads();

        // x-conv (even/odd paired taps on half2 row)
        __half2 h0 = srow[ty][bf][hx + 0];
        __half2 h1 = srow[ty][bf][hx + 1];
        __half2 h2 = srow[ty][bf][hx + 2];
        __half2 h3 = srow[ty][bf][hx + 3];
        __half2 h4 = srow[ty][bf][hx + 4];
        __half2 se = __hmul2(TE[0], h0);
        se = __hfma2(TE[1], h1, se); se = __hfma2(TE[2], h2, se);
        se = __hfma2(TE[3], h3, se); se = __hfma2(TE[4], h4, se);
        __half2 so = __hmul2(TO[0], h0);
        so = __hfma2(TO[1], h1, so); so = __hfma2(TO[2], h2, so);
        so = __hfma2(TO[3], h3, so); so = __hfma2(TO[4], h4, so);
        float2 fe = __half22float2(se);
        float2 fo = __half22float2(so);
        Q[(size_t)z * (NSS / 2)] = __floats2half2_rn(fe.x + fe.y, fo.x + fo.y);

        #pragma unroll
        for (int i = 0; i < 8; i++) ring[i] = ring[i + 1];
    }

    // block-reduce the three sums, write partial slot (no atomics)
    double a = sp, c = sip, d = si;
    #pragma unroll
    for (int o = 16; o > 0; o >>= 1) {
        a += __shfl_down_sync(0xffffffffu, a, o);
        c += __shfl_down_sync(0xffffffffu, c, o);
        d += __shfl_down_sync(0xffffffffu, d, o);
    }
    __shared__ double sm[3][10];
    int tid = ty * 80 + hx;
    int w = tid >> 5, l = tid & 31;
    if (l == 0) { sm[0][w] = a; sm[1][w] = c; sm[2][w] = d; }
    __syncthreads();
    if (tid == 0) {
        double aa = 0, cc = 0, dd = 0;
        for (int i = 0; i < 10; i++) { aa += sm[0][i]; cc += sm[1][i]; dd += sm[2][i]; }
        int pb = ((b * 4 + blockIdx.y) * 40 + blockIdx.x) * 3;
        g_p1[pb + 0] = aa;
        g_p1[pb + 1] = cc;
        g_p1[pb + 2] = dd;
    }
}

// Pass 2: barrier-free streaming. Each thread owns 4 x (2 half2 chains), rings
// over y on q, loads packed (p,v), computes weights + all four dots.
__global__ void __launch_bounds__(320) k_C(float* __restrict__ out) {
    const float G[9] = G_TAPS;
    __half2 G2[9];
    #pragma unroll
    for (int i = 0; i < 9; i++) G2[i] = __float2half2_rn(G[i]);

    int tx = threadIdx.x;          // 0..39 (4 x each)
    int tz = threadIdx.y;          // 0..7
    int z  = blockIdx.x * 8 + tz;
    int y0 = blockIdx.y * ZCH;
    int b  = blockIdx.z;
    int tid = tz * 40 + tx;

    // means from pass-1 partials (warp 0 sums 160 slots)
    __shared__ float s_m[2];
    if (tid < 32) {
        double a = 0, c = 0, d = 0;
        for (int i = tid; i < 160; i += 32) {
            int base = (b * 160 + i) * 3;
            a += g_p1[base + 0]; c += g_p1[base + 1]; d += g_p1[base + 2];
        }
        #pragma unroll
        for (int o = 16; o > 0; o >>= 1) {
            a += __shfl_down_sync(0xffffffffu, a, o);
            c += __shfl_down_sync(0xffffffffu, c, o);
            d += __shfl_down_sync(0xffffffffu, d, o);
        }
        if (tid == 0) {
            const double Nv = (double)NVOX;
            s_m[0] = (float)((c / Nv) / (a / Nv + 1e-5));
            s_m[1] = (float)(((d - c) / Nv) / ((Nv - a) / Nv + 1e-5));
        }
    }
    __syncthreads();
    float m0 = s_m[0], m1 = s_m[1];

    float cz = cfun(z);
    float cc0 = cfun(4 * tx + 0) * cz;
    float cc1 = cfun(4 * tx + 1) * cz;
    float cc2 = cfun(4 * tx + 2) * cz;
    float cc3 = cfun(4 * tx + 3) * cz;

    size_t plane = (size_t)b * NVOX + (size_t)z * NSS;
    const uint2* Qr  = (const uint2*)g_q + plane / 4 + tx;    // uint2 = 2 half2 = 4 x; NS/4=40 per row
    const uint4* PVr = (const uint4*)g_pv + plane / 4 + tx;   // uint4 = 4 half2 = 4 voxels; NS/4 per row

    __half2 r0[9], r1[9];
    const __half2 h2z = __float2half2_rn(0.f);
    #pragma unroll
    for (int i = 0; i < 8; i++) {
        int y = y0 - 4 + i;
        __half2 a = h2z, c = h2z;
        if (y >= 0) {
            uint2 qw = Qr[(size_t)y * (NS / 4)];
            a = u32_as_h2(qw.x);
            c = u32_as_h2(qw.y);
        }
        r0[i] = a; r1[i] = c;
    }

    float aD0 = 0.f, aN0 = 0.f, aD1 = 0.f, aN1 = 0.f;

    #pragma unroll 8
    for (int j = 0; j < ZCH; ++j) {
        int y  = y0 + j;
        int yl = y + 4;
        __half2 a = h2z, c = h2z;
        if (yl < NS) {
            uint2 qw = Qr[(size_t)yl * (NS / 4)];
            a = u32_as_h2(qw.x);
            c = u32_as_h2(qw.y);
        }
        r0[8] = a; r1[8] = c;

        __half2 s0 = __hmul2(G2[0], r0[0]);
        __half2 s1 = __hmul2(G2[0], r1[0]);
        #pragma unroll
        for (int i = 1; i < 9; i++) {
            s0 = __hfma2(G2[i], r0[i], s0);
            s1 = __hfma2(G2[i], r1[i], s1);
        }
        float2 qa = __half22float2(s0);    // q at x=4tx, 4tx+1
        float2 qb = __half22float2(s1);    // q at x=4tx+2, 4tx+3

        float cy = cfun(y);
        float qc0 = cc0 * cy - qa.x;
        float qc1 = cc1 * cy - qa.y;
        float qc2 = cc2 * cy - qb.x;
        float qc3 = cc3 * cy - qb.y;

        uint4 pvw = PVr[(size_t)y * (NS / 4)];
        float2 pv0 = __half22float2(u32_as_h2(pvw.x));
        float2 pv1 = __half22float2(u32_as_h2(pvw.y));
        float2 pv2 = __half22float2(u32_as_h2(pvw.z));
        float2 pv3 = __half22float2(u32_as_h2(pvw.w));

        #define LANE(pv, qv, qcv) { \
            float p = pv.x, v = pv.y; \
            float d0 = v - m0; float u0 = d0 * d0; float w0 = __expf(-u0 * u0); \
            float d1 = v - m1; float u1 = d1 * d1; float w1 = __expf(-u1 * u1); \
            aD0 += w0 * qv;  aN0 += (p * w0) * qv; \
            aD1 += w1 * qcv; aN1 += ((1.f - p) * w1) * qcv; }
        LANE(pv0, qa.x, qc0)
        LANE(pv1, qa.y, qc1)
        LANE(pv2, qb.x, qc2)
        LANE(pv3, qb.y, qc3)
        #undef LANE

        #pragma unroll
        for (int i = 0; i < 8; i++) { r0[i] = r0[i + 1]; r1[i] = r1[i + 1]; }
    }

    // block-reduce four accumulators, write partial, last block finalizes
    double vn0 = aN0, vd0 = aD0, vn1 = aN1, vd1 = aD1;
    #pragma unroll
    for (int o = 16; o > 0; o >>= 1) {
        vn0 += __shfl_down_sync(0xffffffffu, vn0, o);
        vd0 += __shfl_down_sync(0xffffffffu, vd0, o);
        vn1 += __shfl_down_sync(0xffffffffu, vn1, o);
        vd1 += __shfl_down_sync(0xffffffffu, vd1, o);
    }
    __shared__ double sm[4][10];
    int w = tid >> 5, l = tid & 31;
    if (l == 0) { sm[0][w] = vn0; sm[1][w] = vd0; sm[2][w] = vn1; sm[3][w] = vd1; }
    __syncthreads();

    __shared__ int s_last;
    int bid = (b * 4 + blockIdx.y) * 20 + blockIdx.x;
    if (tid == 0) {
        double aa = 0, bb = 0, cc = 0, dd = 0;
        for (int i = 0; i < 10; i++) { aa += sm[0][i]; bb += sm[1][i]; cc += sm[2][i]; dd += sm[3][i]; }
        g_p2[bid * 4 + 0] = aa;
        g_p2[bid * 4 + 1] = bb;
        g_p2[bid * 4 + 2] = cc;
        g_p2[bid * 4 + 3] = dd;
        __threadfence();
        unsigned t = atomicAdd(&g_cnt, 1);
        s_last = (t == NBLK2 - 1);
    }
    __syncthreads();
    if (s_last) {
        double s0 = 0, s1 = 0, s2 = 0, s3 = 0;
        for (int i = tid; i < NBLK2; i += 320) {
            s0 += g_p2[i * 4 + 0];
            s1 += g_p2[i * 4 + 1];
            s2 += g_p2[i * 4 + 2];
            s3 += g_p2[i * 4 + 3];
        }
        #pragma unroll
        for (int o = 16; o > 0; o >>= 1) {
            s0 += __shfl_down_sync(0xffffffffu, s0, o);
            s1 += __shfl_down_sync(0xffffffffu, s1, o);
            s2 += __shfl_down_sync(0xffffffffu, s2, o);
            s3 += __shfl_down_sync(0xffffffffu, s3, o);
        }
        if (l == 0) { sm[0][w] = s0; sm[1][w] = s1; sm[2][w] = s2; sm[3][w] = s3; }
        __syncthreads();
        if (tid == 0) {
            double aa = 0, bb = 0, cc = 0, dd = 0;
            for (int i = 0; i < 10; i++) { aa += sm[0][i]; bb += sm[1][i]; cc += sm[2][i]; dd += sm[3][i]; }
            double loss = fabs(aa / (bb + 1e-6)) + fabs(cc / (dd + 1e-6));
            out[0] = (float)(2.0 - loss);
            g_cnt = 0;   // reset for next graph replay
        }
    }
}

extern "C" void kernel_launch(void* const* d_in, const int* in_sizes, int n_in,
                              void* d_out, int out_size) {
    const float* lab = (const float*)d_in[0];
    const float* inp = (const float*)d_in[1];
    float* out = (float*)d_out;

    k_A<<<dim3(40, 4, NB), dim3(80, 4)>>>(lab, inp);   // sums + zx-conv(p) + pv pack
    k_C<<<dim3(20, 4, NB), dim3(40, 8)>>>(out);        // y-conv + weights + dots + finalize
}